// round 7
// baseline (speedup 1.0000x reference)
#include <cuda_runtime.h>
#include <cstdint>

// Problem constants
#define BB 16
#define NN 2048
#define CC 128
#define MTOT (BB * NN)          // 32768
#define KNN 8

static __device__ float g_pts[MTOT * CC];   // (B,N,C) current features
static __device__ float g_xc [MTOT * CC];   // center = relu(pts) @ Wc^T
static __device__ float g_xg [MTOT * CC];   // pts @ Wg^T
static __device__ int   g_nbr[MTOT * 8];    // slot0 = self, 1..7 neighbors (global row ids)
static __device__ float g_w  [MTOT * 8];    // normalized adjacency weights per slot
static __device__ float g_dis[MTOT];        // deg^-1/2
static __device__ float g_yc [MTOT * 6];
static __device__ float g_yg [MTOT * 6];

#define ALPHA_F (8.0f / 9.0f)
#define OMA_F   (1.0f - 8.0f / 9.0f)

// Packed dual-fp32 FMA (Blackwell FFMA2) — bit-exact IEEE fp32 rn per lane.
// Reachable only via PTX (SASS_QUICKREF: "FFMA2 from C++ ... only via PTX fma.rn.f32x2").
#define FMA_F32X2(d, a, b, c) \
    asm("fma.rn.f32x2 %0, %1, %2, %3;" : "=l"(d) : "l"(a), "l"(b), "l"(c))
#define DUP_F32X2(d, f) \
    asm("mov.b64 %0, {%1, %1};" : "=l"(d) : "r"(__float_as_uint(f)))
#define UNPACK_F32X2(lo, hi, v) \
    asm("mov.b64 {%0, %1}, %2;" : "=r"(lo), "=r"(hi) : "l"(v))

// ---------------------------------------------------------------------------
// kNN: per query point, 8 smallest distances (ties -> lowest index, matching
// jax.lax.top_k of -dist).  dist = x2[i] + x2[j] - 2*inner, forced fp32 rn.
// ---------------------------------------------------------------------------
__global__ __launch_bounds__(256) void knn_kernel(const float* __restrict__ xyz) {
    __shared__ float xs[NN], ys[NN], zs[NN], x2s[NN];
    int b = blockIdx.y;
    const float* base = xyz + (size_t)b * 3 * NN;
    for (int j = threadIdx.x; j < NN; j += 256) {
        float x = base[j], y = base[NN + j], z = base[2 * NN + j];
        xs[j] = x; ys[j] = y; zs[j] = z;
        x2s[j] = __fadd_rn(__fadd_rn(__fmul_rn(x, x), __fmul_rn(y, y)), __fmul_rn(z, z));
    }
    __syncthreads();

    int n = blockIdx.x * 256 + threadIdx.x;     // query index within batch
    float qx = xs[n], qy = ys[n], qz = zs[n], q2 = x2s[n];

    float bd[8]; int bi[8];
#pragma unroll
    for (int t = 0; t < 8; t++) { bd[t] = 3.4e38f; bi[t] = -1; }

    for (int j = 0; j < NN; j++) {
        float inner = __fadd_rn(__fadd_rn(__fmul_rn(qx, xs[j]), __fmul_rn(qy, ys[j])),
                                __fmul_rn(qz, zs[j]));
        float dist = __fsub_rn(__fadd_rn(q2, x2s[j]), __fmul_rn(2.0f, inner));
        if (dist < bd[7]) {
            bd[7] = dist; bi[7] = j;
#pragma unroll
            for (int t = 7; t > 0; t--) {
                if (bd[t] < bd[t - 1]) {   // strict <: equal keeps lower index first
                    float td = bd[t]; bd[t] = bd[t - 1]; bd[t - 1] = td;
                    int   ti = bi[t]; bi[t] = bi[t - 1]; bi[t - 1] = ti;
                }
            }
        }
    }

    int p = b * NN + n;
    g_nbr[p * 8 + 0] = p;                       // self-loop slot
    int deg = 1;
#pragma unroll
    for (int t = 1; t < 8; t++) {               // mirror idx[:, :, 1:]
        g_nbr[p * 8 + t] = b * NN + bi[t];
        if (bi[t] != n) deg++;
    }
    g_dis[p] = rsqrtf((float)deg);
}

// ---------------------------------------------------------------------------
// Adjacency weights: w[p][k] = dis[p] * dis[m]; duplicate-self slots -> 0
// ---------------------------------------------------------------------------
__global__ __launch_bounds__(256) void weights_kernel() {
    int p = blockIdx.x * 256 + threadIdx.x;
    if (p >= MTOT) return;
    float dn = g_dis[p];
#pragma unroll
    for (int k = 0; k < 8; k++) {
        int m = g_nbr[p * 8 + k];
        float w = dn * g_dis[m];
        if (k > 0 && m == p) w = 0.0f;          // self already covered by slot 0
        g_w[p * 8 + k] = w;
    }
}

// ---------------------------------------------------------------------------
// Transpose points (B,C,N) -> g_pts (B,N,C)
// ---------------------------------------------------------------------------
__global__ __launch_bounds__(256) void transpose_in_kernel(const float* __restrict__ points) {
    __shared__ float tile[32][33];
    int b = blockIdx.z;
    int n0 = blockIdx.x * 32, c0 = blockIdx.y * 32;
    int tx = threadIdx.x, ty = threadIdx.y;   // (32,8)
    const float* in = points + (size_t)b * CC * NN;
    float* outp = g_pts + (size_t)b * NN * CC;
#pragma unroll
    for (int r = 0; r < 4; r++)
        tile[ty + 8 * r][tx] = in[(c0 + ty + 8 * r) * NN + n0 + tx];
    __syncthreads();
#pragma unroll
    for (int r = 0; r < 4; r++)
        outp[(n0 + ty + 8 * r) * CC + c0 + tx] = tile[tx][ty + 8 * r];
}

// ---------------------------------------------------------------------------
// Dual GEMM with packed FFMA2: Xc = relu(A)@Wc^T, Xg = A@Wg^T
// A = g_pts (32768 x 128).  Tile 64 x 128, BK=16, 256 threads.
// A and relu(A) stored [k][row] so row-pairs are 64-bit lanes; W scalars are
// lane-duplicated; 32 fma.rn.f32x2 per kk replace 64 FFMA + 8 FMNMX.
// ---------------------------------------------------------------------------
__global__ __launch_bounds__(256) void gemm_dual_kernel(const float* __restrict__ Wc,
                                                        const float* __restrict__ Wg) {
    __shared__ __align__(16) float As [16][72];   // [k][row], 288B row stride (16B mult.)
    __shared__ __align__(16) float Ars[16][72];   // relu(A)
    __shared__ __align__(16) float Wcs[16][132];  // [k][d]
    __shared__ __align__(16) float Wgs[16][132];

    int t = threadIdx.x;
    int tx = t & 31, ty = t >> 5;
    int rowBase = blockIdx.x * 64;
    int arow = t >> 2, akq = t & 3;
    int d0 = t >> 2, kq0 = t & 3;           // W-load lane mapping (q=0)
    int d1 = (t + 256) >> 2, kq1 = t & 3;   // q=1

    const float* aPtr = &g_pts[(size_t)(rowBase + arow) * CC + akq * 4];

    // Packed accumulators [row-pair p][col c]; lanes = rows ty*8+2p, ty*8+2p+1.
    unsigned long long accC[4][4] = {};     // 0 bits == (0.0f, 0.0f)
    unsigned long long accG[4][4] = {};

    // Prologue: load k0 = 0
    float4 a4  = *(const float4*)(aPtr);
    float4 wc0 = *(const float4*)&Wc[d0 * 128 + kq0 * 4];
    float4 wg0 = *(const float4*)&Wg[d0 * 128 + kq0 * 4];
    float4 wc1 = *(const float4*)&Wc[d1 * 128 + kq1 * 4];
    float4 wg1 = *(const float4*)&Wg[d1 * 128 + kq1 * 4];

#pragma unroll 1
    for (int k0 = 0; k0 < 128; k0 += 16) {
        // Store current k-block to smem (A transposed to [k][row], + relu copy)
        As [akq * 4 + 0][arow] = a4.x;  Ars[akq * 4 + 0][arow] = fmaxf(a4.x, 0.0f);
        As [akq * 4 + 1][arow] = a4.y;  Ars[akq * 4 + 1][arow] = fmaxf(a4.y, 0.0f);
        As [akq * 4 + 2][arow] = a4.z;  Ars[akq * 4 + 2][arow] = fmaxf(a4.z, 0.0f);
        As [akq * 4 + 3][arow] = a4.w;  Ars[akq * 4 + 3][arow] = fmaxf(a4.w, 0.0f);
        Wcs[kq0 * 4 + 0][d0] = wc0.x; Wcs[kq0 * 4 + 1][d0] = wc0.y;
        Wcs[kq0 * 4 + 2][d0] = wc0.z; Wcs[kq0 * 4 + 3][d0] = wc0.w;
        Wgs[kq0 * 4 + 0][d0] = wg0.x; Wgs[kq0 * 4 + 1][d0] = wg0.y;
        Wgs[kq0 * 4 + 2][d0] = wg0.z; Wgs[kq0 * 4 + 3][d0] = wg0.w;
        Wcs[kq1 * 4 + 0][d1] = wc1.x; Wcs[kq1 * 4 + 1][d1] = wc1.y;
        Wcs[kq1 * 4 + 2][d1] = wc1.z; Wcs[kq1 * 4 + 3][d1] = wc1.w;
        Wgs[kq1 * 4 + 0][d1] = wg1.x; Wgs[kq1 * 4 + 1][d1] = wg1.y;
        Wgs[kq1 * 4 + 2][d1] = wg1.z; Wgs[kq1 * 4 + 3][d1] = wg1.w;
        __syncthreads();

        // Prefetch next k-block into registers (overlaps FMA loop below)
        int kn = k0 + 16;
        if (kn < 128) {
            a4  = *(const float4*)(aPtr + kn);
            wc0 = *(const float4*)&Wc[d0 * 128 + kn + kq0 * 4];
            wg0 = *(const float4*)&Wg[d0 * 128 + kn + kq0 * 4];
            wc1 = *(const float4*)&Wc[d1 * 128 + kn + kq1 * 4];
            wg1 = *(const float4*)&Wg[d1 * 128 + kn + kq1 * 4];
        }

#pragma unroll
        for (int kk = 0; kk < 16; kk++) {
            float4 wc4 = *(const float4*)&Wcs[kk][tx * 4];
            float4 wg4 = *(const float4*)&Wgs[kk][tx * 4];
            // Row-pairs as 64-bit lanes (warp-uniform address -> LDS broadcast)
            ulonglong2 aA = *(const ulonglong2*)&As [kk][ty * 8];
            ulonglong2 aB = *(const ulonglong2*)&As [kk][ty * 8 + 4];
            ulonglong2 rA = *(const ulonglong2*)&Ars[kk][ty * 8];
            ulonglong2 rB = *(const ulonglong2*)&Ars[kk][ty * 8 + 4];
            unsigned long long ap[4] = {aA.x, aA.y, aB.x, aB.y};
            unsigned long long rp[4] = {rA.x, rA.y, rB.x, rB.y};
            unsigned long long wcd[4], wgd[4];
            DUP_F32X2(wcd[0], wc4.x); DUP_F32X2(wcd[1], wc4.y);
            DUP_F32X2(wcd[2], wc4.z); DUP_F32X2(wcd[3], wc4.w);
            DUP_F32X2(wgd[0], wg4.x); DUP_F32X2(wgd[1], wg4.y);
            DUP_F32X2(wgd[2], wg4.z); DUP_F32X2(wgd[3], wg4.w);
#pragma unroll
            for (int p = 0; p < 4; p++) {
#pragma unroll
                for (int c = 0; c < 4; c++) {
                    FMA_F32X2(accC[p][c], rp[p], wcd[c], accC[p][c]);
                    FMA_F32X2(accG[p][c], ap[p], wgd[c], accG[p][c]);
                }
            }
        }
        __syncthreads();
    }

    // Epilogue: unpack pairs -> two rows each, store float4 per row.
#pragma unroll
    for (int p = 0; p < 4; p++) {
        unsigned int cl[4], ch[4], gl[4], gh[4];
#pragma unroll
        for (int c = 0; c < 4; c++) {
            UNPACK_F32X2(cl[c], ch[c], accC[p][c]);
            UNPACK_F32X2(gl[c], gh[c], accG[p][c]);
        }
        size_t r0 = (size_t)(rowBase + ty * 8 + 2 * p) * CC + tx * 4;
        size_t r1 = r0 + CC;
        *(float4*)&g_xc[r0] = make_float4(__uint_as_float(cl[0]), __uint_as_float(cl[1]),
                                          __uint_as_float(cl[2]), __uint_as_float(cl[3]));
        *(float4*)&g_xc[r1] = make_float4(__uint_as_float(ch[0]), __uint_as_float(ch[1]),
                                          __uint_as_float(ch[2]), __uint_as_float(ch[3]));
        *(float4*)&g_xg[r0] = make_float4(__uint_as_float(gl[0]), __uint_as_float(gl[1]),
                                          __uint_as_float(gl[2]), __uint_as_float(gl[3]));
        *(float4*)&g_xg[r1] = make_float4(__uint_as_float(gh[0]), __uint_as_float(gh[1]),
                                          __uint_as_float(gh[2]), __uint_as_float(gh[3]));
    }
}

// ---------------------------------------------------------------------------
// Sparse combine: pts = OMA * (adj @ Xg) + ALPHA * Xc + pts   (one warp/point)
// ---------------------------------------------------------------------------
__global__ __launch_bounds__(256) void combine_kernel() {
    int gw = (blockIdx.x * 256 + threadIdx.x) >> 5;
    if (gw >= MTOT) return;
    int lane = threadIdx.x & 31;
    int p = gw;
    int c0 = lane * 4;
    float4 acc = make_float4(0.f, 0.f, 0.f, 0.f);
#pragma unroll
    for (int k = 0; k < 8; k++) {
        int m   = g_nbr[p * 8 + k];
        float w = g_w[p * 8 + k];
        float4 v = *(const float4*)&g_xg[(size_t)m * CC + c0];
        acc.x += w * v.x; acc.y += w * v.y; acc.z += w * v.z; acc.w += w * v.w;
    }
    float4 xc = *(const float4*)&g_xc[(size_t)p * CC + c0];
    float4 pt = *(const float4*)&g_pts[(size_t)p * CC + c0];
    float4 o;
    o.x = OMA_F * acc.x + ALPHA_F * xc.x + pt.x;
    o.y = OMA_F * acc.y + ALPHA_F * xc.y + pt.y;
    o.z = OMA_F * acc.z + ALPHA_F * xc.z + pt.z;
    o.w = OMA_F * acc.w + ALPHA_F * xc.w + pt.w;
    *(float4*)&g_pts[(size_t)p * CC + c0] = o;
}

// ---------------------------------------------------------------------------
// Final projections: yc = pts @ Wuc^T, yg = pts @ Wug^T   (C=128 -> 6 each)
// 12 workers per point.
// ---------------------------------------------------------------------------
__global__ __launch_bounds__(252) void finalproj_kernel(const float* __restrict__ Wuc,
                                                        const float* __restrict__ Wug) {
    int id = blockIdx.x * 252 + threadIdx.x;
    int p = id / 12, q = id % 12;
    if (p >= MTOT) return;
    const float* row = &g_pts[(size_t)p * CC];
    const float* w;
    float* dst;
    if (q < 6) { w = &Wuc[q * 128];       dst = &g_yc[p * 6 + q]; }
    else       { w = &Wug[(q - 6) * 128]; dst = &g_yg[p * 6 + q - 6]; }
    float s = 0.f;
#pragma unroll
    for (int d = 0; d < 128; d += 4) {
        float4 a = *(const float4*)&row[d];
        float4 b = *(const float4*)&w[d];
        s += a.x * b.x + a.y * b.y + a.z * b.z + a.w * b.w;
    }
    *dst = s;
}

// ---------------------------------------------------------------------------
// new_xyz: out1[b][c][s*N+n] = ALPHA*yc + OMA*(adj@yg) + xyz
// ---------------------------------------------------------------------------
__global__ __launch_bounds__(256) void final_out1_kernel(const float* __restrict__ xyz,
                                                         float* __restrict__ out1) {
    int p = blockIdx.x * 256 + threadIdx.x;
    if (p >= MTOT) return;
    int b = p >> 11, n = p & (NN - 1);
    float g6[6] = {};
#pragma unroll
    for (int k = 0; k < 8; k++) {
        int m   = g_nbr[p * 8 + k];
        float w = g_w[p * 8 + k];
#pragma unroll
        for (int o = 0; o < 6; o++) g6[o] += w * g_yg[m * 6 + o];
    }
#pragma unroll
    for (int o = 0; o < 6; o++) {
        float v = ALPHA_F * g_yc[p * 6 + o] + OMA_F * g6[o];
        int c = o >> 1, s = o & 1;
        out1[(size_t)b * 3 * 2 * NN + c * 2 * NN + s * NN + n] =
            v + xyz[(size_t)b * 3 * NN + c * NN + n];
    }
}

// ---------------------------------------------------------------------------
// Transpose g_pts (B,N,C) -> out2 (B,C,N)
// ---------------------------------------------------------------------------
__global__ __launch_bounds__(256) void transpose_out_kernel(float* __restrict__ out2) {
    __shared__ float tile[32][33];
    int b = blockIdx.z;
    int n0 = blockIdx.x * 32, c0 = blockIdx.y * 32;
    int tx = threadIdx.x, ty = threadIdx.y;
    const float* in = g_pts + (size_t)b * NN * CC;
    float* outp = out2 + (size_t)b * CC * NN;
#pragma unroll
    for (int r = 0; r < 4; r++)
        tile[ty + 8 * r][tx] = in[(size_t)(n0 + ty + 8 * r) * CC + c0 + tx];
    __syncthreads();
#pragma unroll
    for (int r = 0; r < 4; r++)
        outp[(size_t)(c0 + ty + 8 * r) * NN + n0 + tx] = tile[tx][ty + 8 * r];
}

// ---------------------------------------------------------------------------
extern "C" void kernel_launch(void* const* d_in, const int* in_sizes, int n_in,
                              void* d_out, int out_size) {
    const float* xyz    = (const float*)d_in[0];   // (16,3,2048)
    const float* points = (const float*)d_in[1];   // (16,128,2048)
    const float* Wc     = (const float*)d_in[2];   // (4,128,128)
    const float* Wg     = (const float*)d_in[3];   // (4,128,128)
    const float* Wuc    = (const float*)d_in[4];   // (6,128)
    const float* Wug    = (const float*)d_in[5];   // (6,128)
    float* out = (float*)d_out;
    float* out1 = out;                              // new_xyz: 16*3*4096
    float* out2 = out + (size_t)BB * 3 * 2 * NN;    // points out: 16*128*2048

    // Start the longest dependency chain (knn -> weights) first.
    knn_kernel<<<dim3(NN / 256, BB), 256>>>(xyz);
    weights_kernel<<<MTOT / 256, 256>>>();
    transpose_in_kernel<<<dim3(NN / 32, CC / 32, BB), dim3(32, 8)>>>(points);

    for (int i = 0; i < 4; i++) {
        gemm_dual_kernel<<<MTOT / 64, 256>>>(Wc + (size_t)i * 128 * 128,
                                             Wg + (size_t)i * 128 * 128);
        combine_kernel<<<(MTOT * 32) / 256, 256>>>();
    }

    finalproj_kernel<<<(MTOT * 12 + 251) / 252, 252>>>(Wuc, Wug);
    final_out1_kernel<<<MTOT / 256, 256>>>(xyz, out1);
    transpose_out_kernel<<<dim3(NN / 32, CC / 32, BB), dim3(32, 8)>>>(out2);
}